// round 11
// baseline (speedup 1.0000x reference)
#include <cuda_runtime.h>
#include <cuda_bf16.h>
#include <cstddef>

// Problem constants
#define BB    16
#define SS    4096
#define DD    1024      // D_IN
#define HH    1024
#define DOUT  1024
#define SPLIT 64
#define ROWS  (SS / SPLIT)   // 64 rows per pass1 block

// GEMV tiling (full-K, no splits, no partial buffers)
#define NPW   2                    // n-rows per warp
#define NPB   (8 * NPW)            // 16 n-rows per block
#define KJ    8                    // K chunks: 8 x (32 lanes x f4) = 1024 k

// Scratch: __device__ globals (no cudaMalloc allowed)
__device__ float g_partial[BB * SPLIT * DD];   // pass1 partials, 4 MB
__device__ float g_m[BB * DD];                 // mean, 64 KB
__device__ float g_enc[BB * HH];               // hidden, 64 KB

// ---------------------------------------------------------------------------
// Pass 1: partial sums over S. grid = (SPLIT, B) = (64,16), block = 256.
// __ldcs: evict-first stream of x.
// ---------------------------------------------------------------------------
__global__ __launch_bounds__(256) void pass1_kernel(const float* __restrict__ x) {
    const int split = blockIdx.x;
    const int b     = blockIdx.y;
    const int t     = threadIdx.x;

    const float4* xp = reinterpret_cast<const float4*>(
        x + ((size_t)b * SS + (size_t)split * ROWS) * DD);

    float4 acc = make_float4(0.f, 0.f, 0.f, 0.f);
    #pragma unroll 16
    for (int r = 0; r < ROWS; ++r) {
        float4 v = __ldcs(&xp[(size_t)r * (DD / 4) + t]);
        acc.x += v.x; acc.y += v.y; acc.z += v.z; acc.w += v.w;
    }

    float4* out = reinterpret_cast<float4*>(
        g_partial + ((size_t)b * SPLIT + split) * DD);
    out[t] = acc;
}

// ---------------------------------------------------------------------------
// Pass 2: single-level 64-way reduce + 1/S scale -> g_m. 64 blocks x 256.
// Coalesced across d for every split i; 16-deep unroll for MLP.
// ---------------------------------------------------------------------------
__global__ __launch_bounds__(256) void pass2_kernel() {
    const int idx = blockIdx.x * 256 + threadIdx.x;   // over B*D = 16384
    const int b = idx / DD;
    const int d = idx % DD;

    const float* p = g_partial + (size_t)b * SPLIT * DD + d;
    float s = 0.f;
    #pragma unroll 16
    for (int i = 0; i < SPLIT; ++i) s += p[(size_t)i * DD];

    g_m[idx] = s * (1.0f / (float)SS);
}

// ---------------------------------------------------------------------------
// Full-K GEMV with fused bias — writes the FINAL result, no partials:
//   y[b][n] = sum_k v[b][k] * W[n][k] + bias[n]
// grid = N/16 = 64 blocks, block = 256 (8 warps). No smem, no barriers.
// Warp w owns n-rows {n0+2w, n0+2w+1}. Lane covers k-float4 {j*32+lane}.
// W streamed in 8 chunks of 2 f4 (regs stay ~100); v loads are coalesced
// per-warp from the 64 KB L2-hot activation buffer.
// Butterfly reduce over lanes (31 shuffles); lane L exits holding the output
// with original accumulator index == L (n_local = L>>4, b = L&15).
// ---------------------------------------------------------------------------
__global__ __launch_bounds__(256) void gemv_full_kernel(
    const float* __restrict__ v,
    const float* __restrict__ W,
    const float* __restrict__ bias,
    float* __restrict__ y)
{
    const int t    = threadIdx.x;
    const int warp = t >> 5;
    const int lane = t & 31;
    const int n    = blockIdx.x * NPB + warp * NPW;

    const float4* W4 = reinterpret_cast<const float4*>(W);
    const float4* V4 = reinterpret_cast<const float4*>(v);

    // acc[i], i = n_local*16 + b
    float acc[32];
    #pragma unroll
    for (int i = 0; i < 32; ++i) acc[i] = 0.f;

    #pragma unroll
    for (int j = 0; j < KJ; ++j) {
        const int k4 = j * 32 + lane;                 // f4 index in row
        float4 w0 = W4[(size_t)(n    ) * (DD / 4) + k4];
        float4 w1 = W4[(size_t)(n + 1) * (DD / 4) + k4];
        #pragma unroll
        for (int b = 0; b < BB; ++b) {
            float4 m = V4[(size_t)b * (DD / 4) + k4];
            acc[b]      += m.x * w0.x + m.y * w0.y + m.z * w0.z + m.w * w0.w;
            acc[16 + b] += m.x * w1.x + m.y * w1.y + m.z * w1.z + m.w * w1.w;
        }
    }

    // ---- recursive-halving butterfly: 16+8+4+2+1 = 31 shuffles -----------
    #pragma unroll
    for (int step = 0; step < 5; ++step) {
        const int off = 16 >> step;
        const int m   = 32 >> step;
        const bool hi = (lane & off) != 0;
        #pragma unroll
        for (int i = 0; i < 32; ++i) {           // only i < m/2 active
            if (i < m / 2) {
                float tmp  = hi ? acc[i] : acc[i + m / 2];
                float recv = __shfl_xor_sync(0xffffffffu, tmp, off);
                acc[i] = (hi ? acc[i + m / 2] : acc[i]) + recv;
            }
        }
    }

    // lane holds acc[0] for (n_local = lane>>4, b = lane&15); finish with bias
    const int b_out = lane & 15;
    const int n_out = n + (lane >> 4);
    y[(size_t)b_out * HH + n_out] = acc[0] + bias[n_out];
}

// ---------------------------------------------------------------------------
// Launch. Inputs (metadata order): x, W_enc, b_enc, W_out, b_out.
// 4 launches total: pass1, pass2, gemvA, gemvB.
// ---------------------------------------------------------------------------
extern "C" void kernel_launch(void* const* d_in, const int* in_sizes, int n_in,
                              void* d_out, int out_size)
{
    const float* x     = (const float*)d_in[0];
    const float* W_enc = (const float*)d_in[1];
    const float* b_enc = (const float*)d_in[2];
    const float* W_out = (const float*)d_in[3];
    const float* b_out = (const float*)d_in[4];
    float*       out   = (float*)d_out;

    static float* p_m   = nullptr;
    static float* p_enc = nullptr;
    if (!p_m)   cudaGetSymbolAddress((void**)&p_m,   g_m);
    if (!p_enc) cudaGetSymbolAddress((void**)&p_enc, g_enc);

    // 1) partial sums over S
    pass1_kernel<<<dim3(SPLIT, BB), 256>>>(x);
    // 2) mean (single-level 64-way reduce)
    pass2_kernel<<<64, 256>>>();
    // 3) enc = m @ W_enc^T + b_enc   (final, no partials)
    gemv_full_kernel<<<HH / NPB, 256>>>(p_m, W_enc, b_enc, p_enc);
    // 4) out = enc @ W_out^T + b_out (final, no partials)
    gemv_full_kernel<<<DOUT / NPB, 256>>>(p_enc, W_out, b_out, out);
}

// round 12
// speedup vs baseline: 1.0931x; 1.0931x over previous
#include <cuda_runtime.h>
#include <cuda_bf16.h>
#include <cstddef>

// Problem constants
#define BB    16
#define SS    4096
#define DD    1024      // D_IN
#define HH    1024
#define DOUT  1024
#define SPLIT 64
#define ROWS  (SS / SPLIT)   // 64 rows per pass1 block

#define NBLK  128              // epilogue grid (<148 SMs: co-residency guaranteed)

// Scratch: __device__ globals (no cudaMalloc allowed)
__device__ float g_partial[BB * SPLIT * DD];   // pass1 partials, 4 MB
__device__ float g_m[BB * DD];                 // mean, 64 KB
__device__ float g_pA[2 * BB * HH];            // gemvA partials (KS=2), 128 KB
__device__ float g_pB[2 * BB * DOUT];          // gemvB partials (KS=2), 128 KB

// Grid-barrier state. g_ctr self-resets every barrier (replay-safe);
// g_gen grows monotonically (not output-affecting).
__device__ unsigned g_ctr = 0;
__device__ unsigned g_gen = 0;

__device__ __forceinline__ void grid_bar() {
    __syncthreads();
    if (threadIdx.x == 0) {
        __threadfence();                               // release this block's writes
        volatile unsigned* vgen = &g_gen;
        const unsigned gen = *vgen;                    // read BEFORE arriving
        const unsigned prev = atomicAdd(&g_ctr, 1u);
        if (prev == NBLK - 1u) {
            g_ctr = 0u;                                // reset for next barrier/replay
            __threadfence();
            atomicAdd(&g_gen, 1u);                     // release
        } else {
            while (*vgen == gen) { }                   // spin (L2-coherent)
        }
        __threadfence();                               // acquire
    }
    __syncthreads();
}

// ---------------------------------------------------------------------------
// Pass 1: partial sums over S. grid = (SPLIT, B) = (64,16), block = 256.
// __ldcs: evict-first stream of x.
// ---------------------------------------------------------------------------
__global__ __launch_bounds__(256) void pass1_kernel(const float* __restrict__ x) {
    const int split = blockIdx.x;
    const int b     = blockIdx.y;
    const int t     = threadIdx.x;

    const float4* xp = reinterpret_cast<const float4*>(
        x + ((size_t)b * SS + (size_t)split * ROWS) * DD);

    float4 acc = make_float4(0.f, 0.f, 0.f, 0.f);
    #pragma unroll 16
    for (int r = 0; r < ROWS; ++r) {
        float4 v = __ldcs(&xp[(size_t)r * (DD / 4) + t]);
        acc.x += v.x; acc.y += v.y; acc.z += v.z; acc.w += v.w;
    }

    float4* out = reinterpret_cast<float4*>(
        g_partial + ((size_t)b * SPLIT + split) * DD);
    out[t] = acc;
}

// ---------------------------------------------------------------------------
// GEMV phase body (KS=2 split across blockIdx parity), proven R6 shape.
// acc[i], i = n_local*16 + b; 31-shuffle butterfly leaves lane L holding
// output with original index L (n_local = L>>4, b = L&15).
// ---------------------------------------------------------------------------
__device__ __forceinline__ void gemv_phase(
    int blk, int t,
    const float4* __restrict__ V4,      // activations [BB][256] f4 (MODE 0)
    const float4* __restrict__ PA,      // or partial slices (MODE 1)
    const float4* __restrict__ B4,      // bias f4 (MODE 1)
    const float* __restrict__ W,
    float* __restrict__ pout,
    int mode)
{
    const int ks   = blk & 1;            // k-half: 512 k = 128 f4
    const int ng   = blk >> 1;           // 64 n-groups of 16 rows
    const int warp = t >> 5;
    const int lane = t & 31;
    const int n    = ng * 16 + warp * 2;

    const float4* W4 = reinterpret_cast<const float4*>(W);

    // W: 2 rows x 4 f4/lane, coalesced
    float4 w0[4], w1[4];
    #pragma unroll
    for (int j = 0; j < 4; ++j) {
        const int k4 = ks * 128 + j * 32 + lane;
        w0[j] = W4[(size_t)(n    ) * 256 + k4];
        w1[j] = W4[(size_t)(n + 1) * 256 + k4];
    }

    // bias hoisted for mode 1
    float4 bb[4];
    if (mode == 1) {
        #pragma unroll
        for (int j = 0; j < 4; ++j) bb[j] = B4[ks * 128 + j * 32 + lane];
    }

    float acc[32];
    #pragma unroll
    for (int i = 0; i < 32; ++i) acc[i] = 0.f;

    #pragma unroll
    for (int b = 0; b < BB; ++b) {
        #pragma unroll
        for (int j = 0; j < 4; ++j) {
            const int k4 = ks * 128 + j * 32 + lane;
            float4 m;
            if (mode == 0) {
                m = V4[b * 256 + k4];
            } else {
                float4 a0 = PA[b * 256 + k4];
                float4 a1 = PA[4096 + b * 256 + k4];    // slice 1 at +16K floats
                m.x = a0.x + a1.x + bb[j].x;
                m.y = a0.y + a1.y + bb[j].y;
                m.z = a0.z + a1.z + bb[j].z;
                m.w = a0.w + a1.w + bb[j].w;
            }
            acc[b]      += m.x * w0[j].x + m.y * w0[j].y + m.z * w0[j].z + m.w * w0[j].w;
            acc[16 + b] += m.x * w1[j].x + m.y * w1[j].y + m.z * w1[j].z + m.w * w1[j].w;
        }
    }

    // recursive-halving butterfly: 16+8+4+2+1 = 31 shuffles
    #pragma unroll
    for (int step = 0; step < 5; ++step) {
        const int off = 16 >> step;
        const int m   = 32 >> step;
        const bool hi = (lane & off) != 0;
        #pragma unroll
        for (int i = 0; i < 32; ++i) {
            if (i < m / 2) {
                float tmp  = hi ? acc[i] : acc[i + m / 2];
                float recv = __shfl_xor_sync(0xffffffffu, tmp, off);
                acc[i] = (hi ? acc[i + m / 2] : acc[i]) + recv;
            }
        }
    }

    const int b_out = lane & 15;
    const int n_out = n + (lane >> 4);
    pout[(size_t)ks * (BB * HH) + (size_t)b_out * HH + n_out] = acc[0];
}

// ---------------------------------------------------------------------------
// Fused epilogue: mean -> gemvA -> gemvB -> out, one launch, 3 grid barriers.
// grid = NBLK = 128 blocks, 256 threads.
// ---------------------------------------------------------------------------
__global__ __launch_bounds__(256) void epilogue_kernel(
    const float* __restrict__ W_enc,
    const float* __restrict__ b_enc,
    const float* __restrict__ W_out,
    const float* __restrict__ b_out,
    float* __restrict__ out)
{
    const int t   = threadIdx.x;
    const int blk = blockIdx.x;
    __shared__ float sh[128];

    // ---- P1: mean. 128 outputs/block, 2 threads per output ---------------
    {
        const int half = t >> 7;                 // 0/1
        const int o    = blk * 128 + (t & 127);  // 0..16383
        const int b    = o >> 10;
        const int d    = o & 1023;
        const float* p = g_partial + (size_t)b * SPLIT * DD
                       + (size_t)half * 32 * DD + d;
        float s = 0.f;
        #pragma unroll 8
        for (int i = 0; i < 32; ++i) s += p[(size_t)i * DD];
        if (half) sh[t & 127] = s;
        __syncthreads();
        if (!half) g_m[o] = (s + sh[t]) * (1.0f / (float)SS);
    }
    grid_bar();

    // ---- P2: gemvA = m @ W_enc^T (KS=2 partials) --------------------------
    gemv_phase(blk, t,
               reinterpret_cast<const float4*>(g_m), nullptr, nullptr,
               W_enc, g_pA, /*mode=*/0);
    grid_bar();

    // ---- P3: gemvB = (pA0+pA1+b_enc) @ W_out^T (KS=2 partials) -----------
    gemv_phase(blk, t,
               nullptr, reinterpret_cast<const float4*>(g_pA),
               reinterpret_cast<const float4*>(b_enc),
               W_out, g_pB, /*mode=*/1);
    grid_bar();

    // ---- P4: out = pB0 + pB1 + b_out. 128 idx/block, t < 128 -------------
    if (t < 128) {
        const int idx = blk * 128 + t;           // 0..16383
        out[idx] = g_pB[idx] + g_pB[BB * DOUT + idx] + b_out[idx & (DOUT - 1)];
    }
}

// ---------------------------------------------------------------------------
// Launch. Inputs (metadata order): x, W_enc, b_enc, W_out, b_out.
// 2 launches total.
// ---------------------------------------------------------------------------
extern "C" void kernel_launch(void* const* d_in, const int* in_sizes, int n_in,
                              void* d_out, int out_size)
{
    const float* x     = (const float*)d_in[0];
    const float* W_enc = (const float*)d_in[1];
    const float* b_enc = (const float*)d_in[2];
    const float* W_out = (const float*)d_in[3];
    const float* b_out = (const float*)d_in[4];
    float*       out   = (float*)d_out;

    // 1) partial sums over S
    pass1_kernel<<<dim3(SPLIT, BB), 256>>>(x);
    // 2) fused epilogue: mean + both layers + finalize
    epilogue_kernel<<<NBLK, 256>>>(W_enc, b_enc, W_out, b_out, out);
}

// round 13
// speedup vs baseline: 1.1995x; 1.0973x over previous
#include <cuda_runtime.h>
#include <cuda_bf16.h>
#include <cstddef>

// Problem constants
#define BB    16
#define SS    4096
#define DD    1024      // D_IN
#define HH    1024
#define DOUT  1024
#define SPLIT 64
#define ROWS  (SS / SPLIT)   // 64 rows per pass1 block

// Fused GEMM tiling (R6-proven shape)
#define KS    4                    // K-splits
#define CF4   ((DD / KS) / 4)      // 64 float4 per chunk
#define NBLK  256                  // 2 blocks/SM guaranteed resident

// Scratch: __device__ globals (no cudaMalloc allowed)
__device__ float g_partial[BB * SPLIT * DD];   // pass1 partials, 4 MB
__device__ float g_m4[4 * BB * DD];            // pass2a partials, 256 KB
__device__ float g_m[BB * DD];                 // mean, 64 KB
__device__ float g_enc[BB * HH];               // hidden, 64 KB
__device__ float g_pA[KS * BB * HH];           // gemvA partials, 256 KB
__device__ float g_pB[KS * BB * DOUT];         // gemvB partials, 256 KB

// Grid-barrier state (self-resetting counter: graph-replay-safe)
__device__ unsigned g_ctr = 0;
__device__ unsigned g_gen = 0;

__device__ __forceinline__ void grid_bar() {
    __syncthreads();
    if (threadIdx.x == 0) {
        __threadfence();
        volatile unsigned* vgen = &g_gen;
        const unsigned gen = *vgen;                    // read BEFORE arriving
        const unsigned prev = atomicAdd(&g_ctr, 1u);
        if (prev == NBLK - 1u) {
            g_ctr = 0u;
            __threadfence();
            atomicAdd(&g_gen, 1u);                     // release
        } else {
            while (*vgen == gen) { }
        }
        __threadfence();
    }
    __syncthreads();
}

// ---------------------------------------------------------------------------
// Pass 1: partial sums over S. grid = (SPLIT, B) = (64,16), block = 256.
// ---------------------------------------------------------------------------
__global__ __launch_bounds__(256) void pass1_kernel(const float* __restrict__ x) {
    const int split = blockIdx.x;
    const int b     = blockIdx.y;
    const int t     = threadIdx.x;

    const float4* xp = reinterpret_cast<const float4*>(
        x + ((size_t)b * SS + (size_t)split * ROWS) * DD);

    float4 acc = make_float4(0.f, 0.f, 0.f, 0.f);
    #pragma unroll 16
    for (int r = 0; r < ROWS; ++r) {
        float4 v = __ldcs(&xp[(size_t)r * (DD / 4) + t]);
        acc.x += v.x; acc.y += v.y; acc.z += v.z; acc.w += v.w;
    }

    float4* out = reinterpret_cast<float4*>(
        g_partial + ((size_t)b * SPLIT + split) * DD);
    out[t] = acc;
}

// ---------------------------------------------------------------------------
// Pass 2a: reduce 64 partials in 4 groups of 16 -> g_m4. grid (64,4) x 256.
// ---------------------------------------------------------------------------
__global__ __launch_bounds__(256) void pass2a_kernel() {
    const int idx = blockIdx.x * 256 + threadIdx.x;   // over B*D = 16384
    const int kp  = blockIdx.y;                        // 0..3
    const int b = idx / DD;
    const int d = idx % DD;

    const float* p = g_partial + (size_t)b * SPLIT * DD + (size_t)kp * 16 * DD + d;
    float s = 0.f;
    #pragma unroll
    for (int i = 0; i < 16; ++i) s += p[(size_t)i * DD];

    g_m4[(size_t)kp * (BB * DD) + idx] = s;
}

// ---------------------------------------------------------------------------
// Pass 2b: final 4-way reduce + 1/S scale -> g_m. 64 x 256.
// ---------------------------------------------------------------------------
__global__ __launch_bounds__(256) void pass2b_kernel() {
    const int idx = blockIdx.x * 256 + threadIdx.x;
    float s = g_m4[idx] + g_m4[idx + BB * DD] + g_m4[idx + 2 * BB * DD]
            + g_m4[idx + 3 * BB * DD];
    g_m[idx] = s * (1.0f / (float)SS);
}

// ---------------------------------------------------------------------------
// Butterfly: 31 shuffles; lane L exits holding output with orig index L
// (n_local = L>>4, b = L&15).
// ---------------------------------------------------------------------------
__device__ __forceinline__ float butterfly32(float acc[32], int lane) {
    #pragma unroll
    for (int step = 0; step < 5; ++step) {
        const int off = 16 >> step;
        const int m   = 32 >> step;
        const bool hi = (lane & off) != 0;
        #pragma unroll
        for (int i = 0; i < 32; ++i) {
            if (i < m / 2) {
                float tmp  = hi ? acc[i] : acc[i + m / 2];
                float recv = __shfl_xor_sync(0xffffffffu, tmp, off);
                acc[i] = (hi ? acc[i + m / 2] : acc[i]) + recv;
            }
        }
    }
    return acc[0];
}

// ---------------------------------------------------------------------------
// Fused dual GEMM: gemvA -> reduce(+b_enc) -> gemvB -> finalize(+b_out).
// grid = NBLK = 256 blocks x 256 threads, 2 blocks/SM resident (16 warps/SM).
// Block mapping (both GEMM phases): ks = blk&3, ng = blk>>2, n = ng*16+warp*2.
// KEY EXPERIMENT: W_out registers are loaded in phase A, right after W_enc —
// both 4MB weight streams are in flight concurrently. If the observed
// ~660 GB/s weight stream was latency-limited, total W time ≈ one stream.
// ---------------------------------------------------------------------------
__global__ __launch_bounds__(256, 2) void fused_gemm_kernel(
    const float* __restrict__ W_enc,
    const float* __restrict__ b_enc,
    const float* __restrict__ W_out,
    const float* __restrict__ b_out,
    float* __restrict__ out)
{
    __shared__ float4 sV[BB * CF4];   // 16 KB

    const int t    = threadIdx.x;
    const int blk  = blockIdx.x;
    const int warp = t >> 5;
    const int lane = t & 31;
    const int ks   = blk & 3;
    const int ng   = blk >> 2;            // 0..63
    const int n    = ng * 16 + warp * 2;

    // ---- Phase A: gemvA = m @ W_enc^T --------------------------------------
    // fill sV with m chunk (4 f4 per thread, coalesced)
    {
        const float4* V4 = reinterpret_cast<const float4*>(g_m);
        #pragma unroll
        for (int i = 0; i < 4; ++i) {
            const int id = i * 256 + t;
            const int b  = id >> 6;
            const int k4 = id & 63;
            sV[id] = V4[(size_t)b * (DD / 4) + (size_t)ks * CF4 + k4];
        }
    }
    __syncthreads();

    const size_t wbase = (size_t)ks * CF4 + lane;
    const float4* WE = reinterpret_cast<const float4*>(W_enc);
    float4 w0a = WE[(size_t)(n    ) * (DD / 4) + wbase];
    float4 w0b = WE[(size_t)(n    ) * (DD / 4) + wbase + 32];
    float4 w1a = WE[(size_t)(n + 1) * (DD / 4) + wbase];
    float4 w1b = WE[(size_t)(n + 1) * (DD / 4) + wbase + 32];

    // EARLY W_out preload — in flight concurrently with W_enc + phase A compute
    const float4* WO = reinterpret_cast<const float4*>(W_out);
    float4 o0a = WO[(size_t)(n    ) * (DD / 4) + wbase];
    float4 o0b = WO[(size_t)(n    ) * (DD / 4) + wbase + 32];
    float4 o1a = WO[(size_t)(n + 1) * (DD / 4) + wbase];
    float4 o1b = WO[(size_t)(n + 1) * (DD / 4) + wbase + 32];

    {
        float acc[32];
        #pragma unroll
        for (int i = 0; i < 32; ++i) acc[i] = 0.f;

        #pragma unroll
        for (int b = 0; b < BB; ++b) {
            float4 ma = sV[b * CF4 + lane];
            float4 mb = sV[b * CF4 + lane + 32];
            acc[b]      += ma.x * w0a.x + ma.y * w0a.y + ma.z * w0a.z + ma.w * w0a.w
                         + mb.x * w0b.x + mb.y * w0b.y + mb.z * w0b.z + mb.w * w0b.w;
            acc[16 + b] += ma.x * w1a.x + ma.y * w1a.y + ma.z * w1a.z + ma.w * w1a.w
                         + mb.x * w1b.x + mb.y * w1b.y + mb.z * w1b.z + mb.w * w1b.w;
        }

        const float r = butterfly32(acc, lane);
        const int b_o = lane & 15;
        const int n_o = n + (lane >> 4);
        g_pA[(size_t)ks * (BB * HH) + (size_t)b_o * HH + n_o] = r;
    }
    grid_bar();

    // ---- Phase B: enc = sum(pA slices) + b_enc (64 outputs per block) -----
    if (t < 64) {
        const int idx = blk * 64 + t;               // 0..16383
        float s = b_enc[idx & (HH - 1)];
        #pragma unroll
        for (int j = 0; j < KS; ++j) s += g_pA[(size_t)j * (BB * HH) + idx];
        g_enc[idx] = s;
    }
    grid_bar();

    // ---- Phase C: gemvB = enc @ W_out^T (W_out already in registers) ------
    {
        const float4* V4 = reinterpret_cast<const float4*>(g_enc);
        #pragma unroll
        for (int i = 0; i < 4; ++i) {
            const int id = i * 256 + t;
            const int b  = id >> 6;
            const int k4 = id & 63;
            sV[id] = V4[(size_t)b * (HH / 4) + (size_t)ks * CF4 + k4];
        }
    }
    __syncthreads();

    {
        float acc[32];
        #pragma unroll
        for (int i = 0; i < 32; ++i) acc[i] = 0.f;

        #pragma unroll
        for (int b = 0; b < BB; ++b) {
            float4 ma = sV[b * CF4 + lane];
            float4 mb = sV[b * CF4 + lane + 32];
            acc[b]      += ma.x * o0a.x + ma.y * o0a.y + ma.z * o0a.z + ma.w * o0a.w
                         + mb.x * o0b.x + mb.y * o0b.y + mb.z * o0b.z + mb.w * o0b.w;
            acc[16 + b] += ma.x * o1a.x + ma.y * o1a.y + ma.z * o1a.z + ma.w * o1a.w
                         + mb.x * o1b.x + mb.y * o1b.y + mb.z * o1b.z + mb.w * o1b.w;
        }

        const float r = butterfly32(acc, lane);
        const int b_o = lane & 15;
        const int n_o = n + (lane >> 4);
        g_pB[(size_t)ks * (BB * DOUT) + (size_t)b_o * DOUT + n_o] = r;
    }
    grid_bar();

    // ---- Phase D: out = sum(pB slices) + b_out (64 outputs per block) -----
    if (t < 64) {
        const int idx = blk * 64 + t;               // 0..16383
        float s = b_out[idx & (DOUT - 1)];
        #pragma unroll
        for (int j = 0; j < KS; ++j) s += g_pB[(size_t)j * (BB * DOUT) + idx];
        out[idx] = s;
    }
}

// ---------------------------------------------------------------------------
// Launch. Inputs (metadata order): x, W_enc, b_enc, W_out, b_out.
// 4 launches total.
// ---------------------------------------------------------------------------
extern "C" void kernel_launch(void* const* d_in, const int* in_sizes, int n_in,
                              void* d_out, int out_size)
{
    const float* x     = (const float*)d_in[0];
    const float* W_enc = (const float*)d_in[1];
    const float* b_enc = (const float*)d_in[2];
    const float* W_out = (const float*)d_in[3];
    const float* b_out = (const float*)d_in[4];
    float*       out   = (float*)d_out;

    // 1) partial sums over S
    pass1_kernel<<<dim3(SPLIT, BB), 256>>>(x);
    // 2) mean, two levels
    pass2a_kernel<<<dim3(64, 4), 256>>>();
    pass2b_kernel<<<64, 256>>>();
    // 3) fused dual GEMM + bias epilogue
    fused_gemm_kernel<<<NBLK, 256>>>(W_enc, b_enc, W_out, b_out, out);
}

// round 14
// speedup vs baseline: 1.3042x; 1.0873x over previous
#include <cuda_runtime.h>
#include <cuda_bf16.h>
#include <cstddef>

// Problem constants
#define BB    16
#define SS    4096
#define DD    1024      // D_IN
#define HH    1024
#define DOUT  1024
#define SPLIT 64
#define ROWS  (SS / SPLIT)   // 64 rows per pass1 block

// GEMV tiling: ONE WAVE — 128 blocks x 512 threads (16 warps/SM, 1 blk/SM)
#define KS    4                    // K-splits
#define CF4   ((DD / KS) / 4)      // 64 float4 per chunk
#define NPW   2                    // n-rows per warp
#define NPB   (16 * NPW)           // 32 n-rows per block (16 warps)
#define NG    (HH / NPB)           // 32 n-groups -> grid = 32*4 = 128

// Scratch: __device__ globals (no cudaMalloc allowed)
__device__ float g_partial[BB * SPLIT * DD];   // pass1 partials, 4 MB
__device__ float g_m[BB * DD];                 // mean, 64 KB
__device__ float g_pA[KS * BB * HH];           // gemvA partials, 256 KB
__device__ float g_pB[KS * BB * DOUT];         // gemvB partials, 256 KB

// ---------------------------------------------------------------------------
// Pass 1: partial sums over S. grid = (SPLIT, B) = (64,16), block = 256.
// ---------------------------------------------------------------------------
__global__ __launch_bounds__(256) void pass1_kernel(const float* __restrict__ x) {
    const int split = blockIdx.x;
    const int b     = blockIdx.y;
    const int t     = threadIdx.x;

    const float4* xp = reinterpret_cast<const float4*>(
        x + ((size_t)b * SS + (size_t)split * ROWS) * DD);

    float4 acc = make_float4(0.f, 0.f, 0.f, 0.f);
    #pragma unroll 16
    for (int r = 0; r < ROWS; ++r) {
        float4 v = __ldcs(&xp[(size_t)r * (DD / 4) + t]);
        acc.x += v.x; acc.y += v.y; acc.z += v.z; acc.w += v.w;
    }

    float4* out = reinterpret_cast<float4*>(
        g_partial + ((size_t)b * SPLIT + split) * DD);
    out[t] = acc;
}

// ---------------------------------------------------------------------------
// Pass 2: single-level 64-way reduce + 1/S scale -> g_m. 64 blocks x 256.
// ---------------------------------------------------------------------------
__global__ __launch_bounds__(256) void pass2_kernel() {
    const int idx = blockIdx.x * 256 + threadIdx.x;   // over B*D = 16384
    const int b = idx / DD;
    const int d = idx % DD;

    const float* p = g_partial + (size_t)b * SPLIT * DD + d;
    float s = 0.f;
    #pragma unroll 16
    for (int i = 0; i < SPLIT; ++i) s += p[(size_t)i * DD];

    g_m[idx] = s * (1.0f / (float)SS);
}

// ---------------------------------------------------------------------------
// One-wave GEMV partial (proven R6 inner shape at 512 threads):
//   pout[ks][b][n] = sum_{k in chunk ks} v[b][k] * W[n][k]
// grid = (NG, KS) = (32, 4) = 128 blocks, block = 512 (16 warps).
// Warp w owns n-rows {n0+2w, n0+2w+1}; lane covers f4 {lane, lane+32} of the
// 256-k chunk. Per thread: 4 coalesced W LDG.128, 32 LDS.128, 256 FFMA into
// acc[32], 31-shuffle butterfly; lane L exits with output of original
// accumulator index L (n_local = L>>4, b = L&15).
// MODE 0: v = g_m directly.
// MODE 1: v = sum of 4 g_pA slices + bias  (reduceA fused into the fill).
// ---------------------------------------------------------------------------
template <int MODE>
__global__ __launch_bounds__(512, 1) void gemv_kernel(
    const float* __restrict__ vsrc,
    const float* __restrict__ bias,
    const float* __restrict__ W,
    float* __restrict__ pout)
{
    __shared__ float4 sV[BB * CF4];   // 16 b x 64 f4 = 16 KB

    const int t  = threadIdx.x;
    const int n0 = blockIdx.x * NPB;
    const int ks = blockIdx.y;

    // ---- fill v chunk: 1024 float4, 2 per thread, coalesced --------------
    {
        const float4* V4 = reinterpret_cast<const float4*>(vsrc);
        #pragma unroll
        for (int i = 0; i < 2; ++i) {
            const int id = i * 512 + t;         // 0..1023
            const int b  = id >> 6;
            const int k4 = id & 63;
            const size_t g = (size_t)b * (DD / 4) + (size_t)ks * CF4 + k4;
            float4 v;
            if (MODE == 0) {
                v = V4[g];
            } else {
                float4 a0 = V4[g];
                float4 a1 = V4[g + 4096];       // slice stride BB*HH/4 = 4096 f4
                float4 a2 = V4[g + 2 * 4096];
                float4 a3 = V4[g + 3 * 4096];
                float4 bb = reinterpret_cast<const float4*>(bias)[ks * CF4 + k4];
                v.x = a0.x + a1.x + a2.x + a3.x + bb.x;
                v.y = a0.y + a1.y + a2.y + a3.y + bb.y;
                v.z = a0.z + a1.z + a2.z + a3.z + bb.z;
                v.w = a0.w + a1.w + a2.w + a3.w + bb.w;
            }
            sV[id] = v;
        }
    }
    __syncthreads();

    const int warp = t >> 5;
    const int lane = t & 31;
    const int n    = n0 + warp * NPW;

    // W: 2 rows x 2 float4 per lane, coalesced across lanes
    const float4* W4 = reinterpret_cast<const float4*>(W);
    const size_t wbase = (size_t)ks * CF4 + lane;
    float4 w0a = W4[(size_t)(n    ) * (DD / 4) + wbase];
    float4 w0b = W4[(size_t)(n    ) * (DD / 4) + wbase + 32];
    float4 w1a = W4[(size_t)(n + 1) * (DD / 4) + wbase];
    float4 w1b = W4[(size_t)(n + 1) * (DD / 4) + wbase + 32];

    // acc[i], i = n_local*16 + b
    float acc[32];
    #pragma unroll
    for (int i = 0; i < 32; ++i) acc[i] = 0.f;

    #pragma unroll
    for (int b = 0; b < BB; ++b) {
        float4 ma = sV[b * CF4 + lane];
        float4 mb = sV[b * CF4 + lane + 32];
        acc[b]      += ma.x * w0a.x + ma.y * w0a.y + ma.z * w0a.z + ma.w * w0a.w
                     + mb.x * w0b.x + mb.y * w0b.y + mb.z * w0b.z + mb.w * w0b.w;
        acc[16 + b] += ma.x * w1a.x + ma.y * w1a.y + ma.z * w1a.z + ma.w * w1a.w
                     + mb.x * w1b.x + mb.y * w1b.y + mb.z * w1b.z + mb.w * w1b.w;
    }

    // ---- recursive-halving butterfly: 16+8+4+2+1 = 31 shuffles -----------
    #pragma unroll
    for (int step = 0; step < 5; ++step) {
        const int off = 16 >> step;
        const int m   = 32 >> step;
        const bool hi = (lane & off) != 0;
        #pragma unroll
        for (int i = 0; i < 32; ++i) {           // only i < m/2 active
            if (i < m / 2) {
                float tmp  = hi ? acc[i] : acc[i + m / 2];
                float recv = __shfl_xor_sync(0xffffffffu, tmp, off);
                acc[i] = (hi ? acc[i + m / 2] : acc[i]) + recv;
            }
        }
    }

    // lane holds acc[0] for (n_local = lane>>4, b = lane&15)
    const int b_out = lane & 15;
    const int n_out = n + (lane >> 4);
    pout[(size_t)ks * (BB * HH) + (size_t)b_out * HH + n_out] = acc[0];
}

// ---------------------------------------------------------------------------
// Final reduce: out[b][n] = sum of 4 g_pB slices + b_out[n]. 64 x 256.
// ---------------------------------------------------------------------------
__global__ __launch_bounds__(256) void reduce_out_kernel(
    const float* __restrict__ bias, float* __restrict__ out)
{
    const int idx = blockIdx.x * 256 + threadIdx.x;   // over B*DOUT = 16384
    const int nn = idx & (DOUT - 1);
    float s = bias[nn];
    #pragma unroll
    for (int j = 0; j < KS; ++j) s += g_pB[(size_t)j * (BB * DOUT) + idx];
    out[idx] = s;
}

// ---------------------------------------------------------------------------
// Launch. Inputs (metadata order): x, W_enc, b_enc, W_out, b_out.
// 5 launches: pass1, pass2, gemvA, gemvB(fused reduceA), reduce_out.
// ---------------------------------------------------------------------------
extern "C" void kernel_launch(void* const* d_in, const int* in_sizes, int n_in,
                              void* d_out, int out_size)
{
    const float* x     = (const float*)d_in[0];
    const float* W_enc = (const float*)d_in[1];
    const float* b_enc = (const float*)d_in[2];
    const float* W_out = (const float*)d_in[3];
    const float* b_out = (const float*)d_in[4];
    float*       out   = (float*)d_out;

    static float* p_m  = nullptr;
    static float* p_pA = nullptr;
    if (!p_m)  cudaGetSymbolAddress((void**)&p_m,  g_m);
    if (!p_pA) cudaGetSymbolAddress((void**)&p_pA, g_pA);

    static float* p_pB = nullptr;
    if (!p_pB) cudaGetSymbolAddress((void**)&p_pB, g_pB);

    // 1) partial sums over S
    pass1_kernel<<<dim3(SPLIT, BB), 256>>>(x);
    // 2) mean (single-level 64-way reduce)
    pass2_kernel<<<64, 256>>>();
    // 3) enc partials = m @ W_enc^T  (one wave)
    gemv_kernel<0><<<dim3(NG, KS), 512>>>(p_m, nullptr, W_enc, p_pA);
    // 4) out partials = (sum pA + b_enc) @ W_out^T  (one wave, reduce fused)
    gemv_kernel<1><<<dim3(NG, KS), 512>>>(p_pA, b_enc, W_out, p_pB);
    // 5) final reduce + b_out
    reduce_out_kernel<<<64, 256>>>(b_out, out);
}